// round 7
// baseline (speedup 1.0000x reference)
#include <cuda_runtime.h>
#include <cstddef>

typedef unsigned long long u64;

// M matrix, ROW-PAIR layout (no duplication):
//   g_M[((g*32 + k)*8 + j2)*2 + 0] = U_g[2*j2  ][k]
//   g_M[((g*32 + k)*8 + j2)*2 + 1] = U_g[2*j2+1][k]
// One (g,k) column = 8 u64 (row pairs) = 64 B = 4x LDS.128.
__device__ float g_M[4 * 32 * 8 * 2];

// ---------------------------------------------------------------------------
// Precompute: simulate the weight-only circuit on all 32 basis states for
// each of the 4 generators. Thread t = g*32 + k simulates column k of U_g.
// ---------------------------------------------------------------------------
__global__ void precompute_M_kernel(const float* __restrict__ qp)
{
    int t = threadIdx.x;
    if (t >= 128) return;
    int g = t >> 5;
    int k = t & 31;

    float st[32];
#pragma unroll
    for (int i = 0; i < 32; ++i) st[i] = 0.0f;
    st[k] = 1.0f;

#pragma unroll 1
    for (int d = 0; d < 6; ++d) {
#pragma unroll
        for (int w = 0; w < 5; ++w) {
            float th = qp[g * 30 + d * 5 + w] * 0.5f;
            float s, c;
            __sincosf(th, &s, &c);
            const int stride = 16 >> w;
#pragma unroll
            for (int i = 0; i < 32; ++i) {
                if (i & stride) continue;
                float a0 = st[i];
                float a1 = st[i + stride];
                st[i]          = c * a0 - s * a1;
                st[i + stride] = s * a0 + c * a1;
            }
        }
#pragma unroll
        for (int w = 0; w < 4; ++w) {
            const int m = (16 >> w) | (8 >> w);
#pragma unroll
            for (int i = 0; i < 32; ++i)
                if ((i & m) == m) st[i] = -st[i];
        }
    }

#pragma unroll
    for (int j2 = 0; j2 < 8; ++j2) {
        g_M[((g * 32 + k) * 8 + j2) * 2 + 0] = st[2 * j2 + 0];
        g_M[((g * 32 + k) * 8 + j2) * 2 + 1] = st[2 * j2 + 1];
    }
}

// ---------------------------------------------------------------------------
// Packed f32x2 helpers (Blackwell sm_103a)
// ---------------------------------------------------------------------------
__device__ __forceinline__ u64 pk2(float lo, float hi) {
    u64 r;
    asm("mov.b64 %0, {%1, %2};" : "=l"(r) : "f"(lo), "f"(hi));
    return r;
}
__device__ __forceinline__ void upk2(u64 v, float& lo, float& hi) {
    asm("mov.b64 {%0, %1}, %2;" : "=f"(lo), "=f"(hi) : "l"(v));
}
__device__ __forceinline__ u64 fma2(u64 a, u64 b, u64 c) {
    u64 d;
    asm("fma.rn.f32x2 %0, %1, %2, %3;" : "=l"(d) : "l"(a), "l"(b), "l"(c));
    return d;
}

// Scalar Kronecker factors for ONE batch element.
__device__ __forceinline__ void build_psi_scalar(
    float4 q, float pa[8], float pb[4])
{
    float a0 = q.x, a1 = q.y, a2 = q.z;
    float h0 = 0.5f   * a0;
    float h1 = 0.375f * a0 + 0.125f * a1;
    float h2 = 0.125f * a0 + 0.375f * a1;
    float h3 = 0.375f * a1 + 0.125f * a2;
    float h4 = 0.125f * a1 + 0.375f * a2;
    float c0, s0, c1, s1, c2, s2, c3, s3, c4, s4;
    __sincosf(h0, &s0, &c0);
    __sincosf(h1, &s1, &c1);
    __sincosf(h2, &s2, &c2);
    __sincosf(h3, &s3, &c3);
    __sincosf(h4, &s4, &c4);
    float t00 = c0 * c1, t01 = c0 * s1, t10 = s0 * c1, t11 = s0 * s1;
    pa[0] = t00 * c2; pa[1] = t00 * s2;
    pa[2] = t01 * c2; pa[3] = t01 * s2;
    pa[4] = t10 * c2; pa[5] = t10 * s2;
    pa[6] = t11 * c2; pa[7] = t11 * s2;
    pb[0] = c3 * c4; pb[1] = c3 * s4;
    pb[2] = s3 * c4; pb[3] = s3 * s4;
}

// ---------------------------------------------------------------------------
// Main kernel: 4 batch elements/thread, scalar psi, f32x2 packs TWO OUTPUT
// ROWS, M unique in smem (8 KB). Each LDS.128 of M feeds 4 elements.
// ---------------------------------------------------------------------------
__global__ void __launch_bounds__(128, 3) qsrgan_main_kernel(
    const float* __restrict__ in,
    float* __restrict__ out,
    int B)
{
    __shared__ __align__(16) float sM[4 * 32 * 8 * 2];  // 8 KB
    {
        const float4* src = (const float4*)g_M;
        float4* dst = (float4*)sM;
#pragma unroll
        for (int i = threadIdx.x; i < 512; i += 128)
            dst[i] = src[i];
    }
    __syncthreads();

    long long b = ((long long)blockIdx.x * 128 + threadIdx.x) * 4;
    if (b >= B) return;
    long long i1 = (b + 1 < B) ? b + 1 : b;
    long long i2 = (b + 2 < B) ? b + 2 : b;
    long long i3 = (b + 3 < B) ? b + 3 : b;

    float4 q0 = __ldg((const float4*)(in + b  * 16));
    float4 q1 = __ldg((const float4*)(in + i1 * 16));
    float4 q2 = __ldg((const float4*)(in + i2 * 16));
    float4 q3 = __ldg((const float4*)(in + i3 * 16));

    float paA[8], pbA[4], paB[8], pbB[4], paC[8], pbC[4], paD[8], pbD[4];
    build_psi_scalar(q0, paA, pbA);
    build_psi_scalar(q1, paB, pbB);
    build_psi_scalar(q2, paC, pbC);
    build_psi_scalar(q3, paD, pbD);

#pragma unroll 1
    for (int g = 0; g < 4; ++g) {
        // acc[j2][e]: rows (2*j2, 2*j2+1) of element e
        u64 acc[8][4];
#pragma unroll
        for (int j2 = 0; j2 < 8; ++j2)
#pragma unroll
            for (int e = 0; e < 4; ++e) acc[j2][e] = 0ULL;

#pragma unroll 4
        for (int k = 0; k < 32; ++k) {
            const int ka = k >> 2, kb = k & 3;
            float pk0 = paA[ka] * pbA[kb];
            float pk1 = paB[ka] * pbB[kb];
            float pk2v = paC[ka] * pbC[kb];
            float pk3 = paD[ka] * pbD[kb];
            u64 P0 = pk2(pk0, pk0);
            u64 P1 = pk2(pk1, pk1);
            u64 P2 = pk2(pk2v, pk2v);
            u64 P3 = pk2(pk3, pk3);

            const ulonglong2* col = (const ulonglong2*)sM + (g * 32 + k) * 4;
#pragma unroll
            for (int j4 = 0; j4 < 4; ++j4) {
                ulonglong2 mv = col[j4];
                acc[2 * j4 + 0][0] = fma2(mv.x, P0, acc[2 * j4 + 0][0]);
                acc[2 * j4 + 0][1] = fma2(mv.x, P1, acc[2 * j4 + 0][1]);
                acc[2 * j4 + 0][2] = fma2(mv.x, P2, acc[2 * j4 + 0][2]);
                acc[2 * j4 + 0][3] = fma2(mv.x, P3, acc[2 * j4 + 0][3]);
                acc[2 * j4 + 1][0] = fma2(mv.y, P0, acc[2 * j4 + 1][0]);
                acc[2 * j4 + 1][1] = fma2(mv.y, P1, acc[2 * j4 + 1][1]);
                acc[2 * j4 + 1][2] = fma2(mv.y, P2, acc[2 * j4 + 1][2]);
                acc[2 * j4 + 1][3] = fma2(mv.y, P3, acc[2 * j4 + 1][3]);
            }
        }

        // Pass 1: per-element max of squares
        float mx[4] = {0.0f, 0.0f, 0.0f, 0.0f};
#pragma unroll
        for (int j2 = 0; j2 < 8; ++j2) {
#pragma unroll
            for (int e = 0; e < 4; ++e) {
                float y0, y1;
                upk2(acc[j2][e], y0, y1);
                mx[e] = fmaxf(mx[e], fmaxf(y0 * y0, y1 * y1));
            }
        }
        float rc[4];
#pragma unroll
        for (int e = 0; e < 4; ++e) rc[e] = __fdividef(1.0f, mx[e]);

        // Pass 2: squares from acc, scale, store float4 per 4 rows
        float* optr[4];
        optr[0] = out + b  * 64 + g * 16;
        optr[1] = out + i1 * 64 + g * 16;
        optr[2] = out + i2 * 64 + g * 16;
        optr[3] = out + i3 * 64 + g * 16;
        bool wr[4] = {true, b + 1 < B, b + 2 < B, b + 3 < B};

#pragma unroll
        for (int e = 0; e < 4; ++e) {
            if (!wr[e]) continue;
            float r = rc[e];
#pragma unroll
            for (int q = 0; q < 4; ++q) {
                float y0, y1, y2, y3;
                upk2(acc[2 * q + 0][e], y0, y1);
                upk2(acc[2 * q + 1][e], y2, y3);
                ((float4*)optr[e])[q] =
                    make_float4(y0 * y0 * r, y1 * y1 * r, y2 * y2 * r, y3 * y3 * r);
            }
        }
    }
}

// ---------------------------------------------------------------------------
extern "C" void kernel_launch(void* const* d_in, const int* in_sizes, int n_in,
                              void* d_out, int out_size)
{
    const float* in = (const float*)d_in[0];   // (B,1,4,4) f32
    const float* qp = (const float*)d_in[1];   // (4, 30) f32
    float* out = (float*)d_out;                // (B, 64) f32

    int B = in_sizes[0] / 16;
    int nthreads = (B + 3) / 4;
    int blocks = (nthreads + 127) / 128;

    precompute_M_kernel<<<1, 128>>>(qp);
    qsrgan_main_kernel<<<blocks, 128>>>(in, out, B);
}

// round 8
// speedup vs baseline: 1.2584x; 1.2584x over previous
#include <cuda_runtime.h>
#include <cstddef>

typedef unsigned long long u64;

// M matrix, ROW-PAIR layout (no duplication):
//   g_M[((g*32 + k)*8 + j2)*2 + 0] = U_g[2*j2  ][k]
//   g_M[((g*32 + k)*8 + j2)*2 + 1] = U_g[2*j2+1][k]
// One (g,k) column = 8 u64 (row pairs) = 64 B = 2x LDS.128.
__device__ float g_M[4 * 32 * 8 * 2];

// ---------------------------------------------------------------------------
// Precompute: simulate the weight-only circuit on all 32 basis states for
// each of the 4 generators. Thread t = g*32 + k simulates column k of U_g.
// ---------------------------------------------------------------------------
__global__ void precompute_M_kernel(const float* __restrict__ qp)
{
    int t = threadIdx.x;
    if (t >= 128) return;
    int g = t >> 5;
    int k = t & 31;

    float st[32];
#pragma unroll
    for (int i = 0; i < 32; ++i) st[i] = 0.0f;
    st[k] = 1.0f;

#pragma unroll 1
    for (int d = 0; d < 6; ++d) {
#pragma unroll
        for (int w = 0; w < 5; ++w) {
            float th = qp[g * 30 + d * 5 + w] * 0.5f;
            float s, c;
            sincosf(th, &s, &c);
            const int stride = 16 >> w;
#pragma unroll
            for (int i = 0; i < 32; ++i) {
                if (i & stride) continue;
                float a0 = st[i];
                float a1 = st[i + stride];
                st[i]          = c * a0 - s * a1;
                st[i + stride] = s * a0 + c * a1;
            }
        }
#pragma unroll
        for (int w = 0; w < 4; ++w) {
            const int m = (16 >> w) | (8 >> w);
#pragma unroll
            for (int i = 0; i < 32; ++i)
                if ((i & m) == m) st[i] = -st[i];
        }
    }

#pragma unroll
    for (int j2 = 0; j2 < 8; ++j2) {
        g_M[((g * 32 + k) * 8 + j2) * 2 + 0] = st[2 * j2 + 0];
        g_M[((g * 32 + k) * 8 + j2) * 2 + 1] = st[2 * j2 + 1];
    }
}

// ---------------------------------------------------------------------------
// Packed f32x2 helpers (Blackwell sm_103a)
// ---------------------------------------------------------------------------
__device__ __forceinline__ u64 pk2(float lo, float hi) {
    u64 r;
    asm("mov.b64 %0, {%1, %2};" : "=l"(r) : "f"(lo), "f"(hi));
    return r;
}
__device__ __forceinline__ void upk2(u64 v, float& lo, float& hi) {
    asm("mov.b64 {%0, %1}, %2;" : "=f"(lo), "=f"(hi) : "l"(v));
}
__device__ __forceinline__ u64 fma2(u64 a, u64 b, u64 c) {
    u64 d;
    asm("fma.rn.f32x2 %0, %1, %2, %3;" : "=l"(d) : "l"(a), "l"(b), "l"(c));
    return d;
}
__device__ __forceinline__ u64 mul2(u64 a, u64 b) {
    u64 d;
    asm("mul.rn.f32x2 %0, %1, %2;" : "=l"(d) : "l"(a), "l"(b));
    return d;
}

// ---------------------------------------------------------------------------
// Main kernel: ONE element per thread, minimal registers, psi Kronecker
// factors pre-splatted into u64 so the k-loop is pure fma-pipe:
//   pk = mul2(pa[ka], pb[kb]);  8x fma2
// M unique in smem (8 KB), f32x2 packs TWO OUTPUT ROWS.
// ---------------------------------------------------------------------------
__global__ void __launch_bounds__(256, 3) qsrgan_main_kernel(
    const float* __restrict__ in,
    float* __restrict__ out,
    int B)
{
    __shared__ __align__(16) float sM[4 * 32 * 8 * 2];  // 8 KB
    {
        const float4* src = (const float4*)g_M;
        float4* dst = (float4*)sM;
#pragma unroll
        for (int i = threadIdx.x; i < 512; i += 256)
            dst[i] = src[i];
    }
    __syncthreads();

    long long b = (long long)blockIdx.x * 256 + threadIdx.x;
    if (b >= B) return;

    float4 q = __ldg((const float4*)(in + b * 16));

    // Build splatted Kronecker factors (one-time cost, ~22 movs).
    u64 pa[8], pb[4];
    {
        float a0 = q.x, a1 = q.y, a2 = q.z;
        float h0 = 0.5f   * a0;
        float h1 = 0.375f * a0 + 0.125f * a1;
        float h2 = 0.125f * a0 + 0.375f * a1;
        float h3 = 0.375f * a1 + 0.125f * a2;
        float h4 = 0.125f * a1 + 0.375f * a2;
        float c0, s0, c1, s1, c2, s2, c3, s3, c4, s4;
        __sincosf(h0, &s0, &c0);
        __sincosf(h1, &s1, &c1);
        __sincosf(h2, &s2, &c2);
        __sincosf(h3, &s3, &c3);
        __sincosf(h4, &s4, &c4);
        float t00 = c0 * c1, t01 = c0 * s1, t10 = s0 * c1, t11 = s0 * s1;
        float paf[8], pbf[4];
        paf[0] = t00 * c2; paf[1] = t00 * s2;
        paf[2] = t01 * c2; paf[3] = t01 * s2;
        paf[4] = t10 * c2; paf[5] = t10 * s2;
        paf[6] = t11 * c2; paf[7] = t11 * s2;
        pbf[0] = c3 * c4;  pbf[1] = c3 * s4;
        pbf[2] = s3 * c4;  pbf[3] = s3 * s4;
#pragma unroll
        for (int i = 0; i < 8; ++i) pa[i] = pk2(paf[i], paf[i]);
#pragma unroll
        for (int i = 0; i < 4; ++i) pb[i] = pk2(pbf[i], pbf[i]);
    }

    float* optr = out + b * 64;

#pragma unroll 1
    for (int g = 0; g < 4; ++g) {
        u64 acc[8];   // acc[j2] = rows (2*j2, 2*j2+1)
#pragma unroll
        for (int j2 = 0; j2 < 8; ++j2) acc[j2] = 0ULL;

#pragma unroll 8
        for (int k = 0; k < 32; ++k) {
            u64 pk = mul2(pa[k >> 2], pb[k & 3]);
            const ulonglong2* col = (const ulonglong2*)sM + (g * 32 + k) * 4;
#pragma unroll
            for (int j4 = 0; j4 < 4; ++j4) {
                ulonglong2 mv = col[j4];
                acc[2 * j4 + 0] = fma2(mv.x, pk, acc[2 * j4 + 0]);
                acc[2 * j4 + 1] = fma2(mv.y, pk, acc[2 * j4 + 1]);
            }
        }

        // Epilogue: square (packed), max, scale, store.
        u64 sq[8];
        float mx = 0.0f;
#pragma unroll
        for (int j2 = 0; j2 < 8; ++j2) {
            sq[j2] = mul2(acc[j2], acc[j2]);
            float y0, y1;
            upk2(sq[j2], y0, y1);
            mx = fmaxf(mx, fmaxf(y0, y1));
        }
        float r = __fdividef(1.0f, mx);
#pragma unroll
        for (int qd = 0; qd < 4; ++qd) {
            float y0, y1, y2, y3;
            upk2(sq[2 * qd + 0], y0, y1);
            upk2(sq[2 * qd + 1], y2, y3);
            ((float4*)(optr + g * 16))[qd] =
                make_float4(y0 * r, y1 * r, y2 * r, y3 * r);
        }
    }
}

// ---------------------------------------------------------------------------
extern "C" void kernel_launch(void* const* d_in, const int* in_sizes, int n_in,
                              void* d_out, int out_size)
{
    const float* in = (const float*)d_in[0];   // (B,1,4,4) f32
    const float* qp = (const float*)d_in[1];   // (4, 30) f32
    float* out = (float*)d_out;                // (B, 64) f32

    int B = in_sizes[0] / 16;
    int blocks = (B + 255) / 256;

    precompute_M_kernel<<<1, 128>>>(qp);
    qsrgan_main_kernel<<<blocks, 256>>>(in, out, B);
}

// round 9
// speedup vs baseline: 1.3007x; 1.0337x over previous
#include <cuda_runtime.h>
#include <cstddef>

typedef unsigned long long u64;

// M matrix, ROW-PAIR layout (no duplication):
//   [((g*32 + k)*8 + j2)*2 + 0] = U_g[2*j2  ][k]
//   [((g*32 + k)*8 + j2)*2 + 1] = U_g[2*j2+1][k]
// 2048 floats = 8 KB. Staged in global by the precompute kernel, then copied
// into constant memory so the mainloop reads via the constant port (LDC) —
// zero shared-memory crossbar traffic.
__device__ float g_M[4 * 32 * 8 * 2];

// Same bytes, viewed as ulonglong2 so device code emits LDC.128 from
// constant space (one (g,k) column = 4 ulonglong2 = 64 B).
__constant__ ulonglong2 cM[4 * 32 * 4];

// ---------------------------------------------------------------------------
// Precompute: simulate the weight-only circuit on all 32 basis states for
// each of the 4 generators. Thread t = g*32 + k simulates column k of U_g.
// ---------------------------------------------------------------------------
__global__ void precompute_M_kernel(const float* __restrict__ qp)
{
    int t = threadIdx.x;
    if (t >= 128) return;
    int g = t >> 5;
    int k = t & 31;

    float st[32];
#pragma unroll
    for (int i = 0; i < 32; ++i) st[i] = 0.0f;
    st[k] = 1.0f;

#pragma unroll 1
    for (int d = 0; d < 6; ++d) {
#pragma unroll
        for (int w = 0; w < 5; ++w) {
            float th = qp[g * 30 + d * 5 + w] * 0.5f;
            float s, c;
            __sincosf(th, &s, &c);
            const int stride = 16 >> w;
#pragma unroll
            for (int i = 0; i < 32; ++i) {
                if (i & stride) continue;
                float a0 = st[i];
                float a1 = st[i + stride];
                st[i]          = c * a0 - s * a1;
                st[i + stride] = s * a0 + c * a1;
            }
        }
#pragma unroll
        for (int w = 0; w < 4; ++w) {
            const int m = (16 >> w) | (8 >> w);
#pragma unroll
            for (int i = 0; i < 32; ++i)
                if ((i & m) == m) st[i] = -st[i];
        }
    }

#pragma unroll
    for (int j2 = 0; j2 < 8; ++j2) {
        g_M[((g * 32 + k) * 8 + j2) * 2 + 0] = st[2 * j2 + 0];
        g_M[((g * 32 + k) * 8 + j2) * 2 + 1] = st[2 * j2 + 1];
    }
}

// ---------------------------------------------------------------------------
// Packed f32x2 helpers (Blackwell sm_103a)
// ---------------------------------------------------------------------------
__device__ __forceinline__ u64 pk2(float lo, float hi) {
    u64 r;
    asm("mov.b64 %0, {%1, %2};" : "=l"(r) : "f"(lo), "f"(hi));
    return r;
}
__device__ __forceinline__ void upk2(u64 v, float& lo, float& hi) {
    asm("mov.b64 {%0, %1}, %2;" : "=f"(lo), "=f"(hi) : "l"(v));
}
__device__ __forceinline__ u64 fma2(u64 a, u64 b, u64 c) {
    u64 d;
    asm("fma.rn.f32x2 %0, %1, %2, %3;" : "=l"(d) : "l"(a), "l"(b), "l"(c));
    return d;
}
__device__ __forceinline__ u64 mul2(u64 a, u64 b) {
    u64 d;
    asm("mul.rn.f32x2 %0, %1, %2;" : "=l"(d) : "l"(a), "l"(b));
    return d;
}

// Scalar Kronecker factors for ONE batch element.
__device__ __forceinline__ void build_psi_scalar(
    float4 q, float pa[8], float pb[4])
{
    float a0 = q.x, a1 = q.y, a2 = q.z;
    float h0 = 0.5f   * a0;
    float h1 = 0.375f * a0 + 0.125f * a1;
    float h2 = 0.125f * a0 + 0.375f * a1;
    float h3 = 0.375f * a1 + 0.125f * a2;
    float h4 = 0.125f * a1 + 0.375f * a2;
    float c0, s0, c1, s1, c2, s2, c3, s3, c4, s4;
    __sincosf(h0, &s0, &c0);
    __sincosf(h1, &s1, &c1);
    __sincosf(h2, &s2, &c2);
    __sincosf(h3, &s3, &c3);
    __sincosf(h4, &s4, &c4);
    float t00 = c0 * c1, t01 = c0 * s1, t10 = s0 * c1, t11 = s0 * s1;
    pa[0] = t00 * c2; pa[1] = t00 * s2;
    pa[2] = t01 * c2; pa[3] = t01 * s2;
    pa[4] = t10 * c2; pa[5] = t10 * s2;
    pa[6] = t11 * c2; pa[7] = t11 * s2;
    pb[0] = c3 * c4; pb[1] = c3 * s4;
    pb[2] = s3 * c4; pb[3] = s3 * s4;
}

// ---------------------------------------------------------------------------
// Main kernel: 2 batch elements/thread, scalar psi, M read from CONSTANT
// memory (LDC — dedicated port, no smem crossbar). f32x2 packs TWO OUTPUT
// ROWS per accumulator.
// ---------------------------------------------------------------------------
__global__ void __launch_bounds__(128, 4) qsrgan_main_kernel(
    const float* __restrict__ in,
    float* __restrict__ out,
    int B)
{
    long long b = ((long long)blockIdx.x * 128 + threadIdx.x) * 2;
    if (b >= B) return;
    long long i1 = (b + 1 < B) ? b + 1 : b;

    float4 q0 = __ldg((const float4*)(in + b  * 16));
    float4 q1 = __ldg((const float4*)(in + i1 * 16));

    float paA[8], pbA[4], paB[8], pbB[4];
    build_psi_scalar(q0, paA, pbA);
    build_psi_scalar(q1, paB, pbB);

#pragma unroll 1
    for (int g = 0; g < 4; ++g) {
        // acc[j2][e]: rows (2*j2, 2*j2+1) of element e
        u64 acc[8][2];
#pragma unroll
        for (int j2 = 0; j2 < 8; ++j2) { acc[j2][0] = 0ULL; acc[j2][1] = 0ULL; }

#pragma unroll 8
        for (int k = 0; k < 32; ++k) {
            float pk0 = paA[k >> 2] * pbA[k & 3];
            float pk1 = paB[k >> 2] * pbB[k & 3];
            u64 P0 = pk2(pk0, pk0);
            u64 P1 = pk2(pk1, pk1);

#pragma unroll
            for (int j4 = 0; j4 < 4; ++j4) {
                ulonglong2 mv = cM[(g * 32 + k) * 4 + j4];
                acc[2 * j4 + 0][0] = fma2(mv.x, P0, acc[2 * j4 + 0][0]);
                acc[2 * j4 + 0][1] = fma2(mv.x, P1, acc[2 * j4 + 0][1]);
                acc[2 * j4 + 1][0] = fma2(mv.y, P0, acc[2 * j4 + 1][0]);
                acc[2 * j4 + 1][1] = fma2(mv.y, P1, acc[2 * j4 + 1][1]);
            }
        }

        // Epilogue: packed squares, per-element max, scale, store.
        u64 sq0[8], sq1[8];
        float mx0 = 0.0f, mx1 = 0.0f;
#pragma unroll
        for (int j2 = 0; j2 < 8; ++j2) {
            sq0[j2] = mul2(acc[j2][0], acc[j2][0]);
            sq1[j2] = mul2(acc[j2][1], acc[j2][1]);
            float y0, y1, z0, z1;
            upk2(sq0[j2], y0, y1);
            upk2(sq1[j2], z0, z1);
            mx0 = fmaxf(mx0, fmaxf(y0, y1));
            mx1 = fmaxf(mx1, fmaxf(z0, z1));
        }
        float r0 = __fdividef(1.0f, mx0);
        float r1 = __fdividef(1.0f, mx1);

        float* o0 = out + b  * 64 + g * 16;
#pragma unroll
        for (int qd = 0; qd < 4; ++qd) {
            float y0, y1, y2, y3;
            upk2(sq0[2 * qd + 0], y0, y1);
            upk2(sq0[2 * qd + 1], y2, y3);
            ((float4*)o0)[qd] = make_float4(y0 * r0, y1 * r0, y2 * r0, y3 * r0);
        }
        if (b + 1 < B) {
            float* o1 = out + i1 * 64 + g * 16;
#pragma unroll
            for (int qd = 0; qd < 4; ++qd) {
                float z0, z1, z2, z3;
                upk2(sq1[2 * qd + 0], z0, z1);
                upk2(sq1[2 * qd + 1], z2, z3);
                ((float4*)o1)[qd] = make_float4(z0 * r1, z1 * r1, z2 * r1, z3 * r1);
            }
        }
    }
}

// ---------------------------------------------------------------------------
extern "C" void kernel_launch(void* const* d_in, const int* in_sizes, int n_in,
                              void* d_out, int out_size)
{
    const float* in = (const float*)d_in[0];   // (B,1,4,4) f32
    const float* qp = (const float*)d_in[1];   // (4, 30) f32
    float* out = (float*)d_out;                // (B, 64) f32

    int B = in_sizes[0] / 16;
    int nthreads = (B + 1) / 2;
    int blocks = (nthreads + 127) / 128;

    precompute_M_kernel<<<1, 128>>>(qp);

    // Stage M into constant memory (device-to-device async copy:
    // graph-capturable memcpy node, no allocation).
    void* gM_ptr = nullptr;
    cudaGetSymbolAddress(&gM_ptr, g_M);
    cudaMemcpyToSymbolAsync(cM, gM_ptr, sizeof(float) * 2048, 0,
                            cudaMemcpyDeviceToDevice, 0);

    qsrgan_main_kernel<<<blocks, 128>>>(in, out, B);
}

// round 12
// speedup vs baseline: 1.6508x; 1.2692x over previous
#include <cuda_runtime.h>
#include <cstddef>
#include <cstdint>

typedef unsigned long long u64;

// M matrix in DUAL-PORT split layout (2048 floats total):
//   floats [0, 1024):  SMEM half — rows 0..7  as row-pairs j2=0..3
//       g_M[((g*32 + k)*4 + j2)*2 + {0,1}] = U_g[2*j2 ][k], U_g[2*j2+1][k]
//   floats [1024,2048): CONST half — rows 8..15 as row-pairs j2=4..7
//       g_M[1024 + ((g*32 + k)*4 + (j2-4))*2 + {0,1}]
// The const half is copied into cM (constant memory) so the mainloop reads
// rows 0..7 via the LSU/smem crossbar and rows 8..15 via the constant port —
// two independent hardware paths, each at half traffic.
__device__ float g_M[2048];
__constant__ ulonglong2 cM[256];   // 4 KB: (g*32+k)*2 + c, c=0..1 -> j2 4..7

// ---------------------------------------------------------------------------
// Precompute: simulate the weight-only circuit on all 32 basis states for
// each of the 4 generators. Thread t = g*32 + k simulates column k of U_g.
// ---------------------------------------------------------------------------
__global__ void precompute_M_kernel(const float* __restrict__ qp)
{
    int t = threadIdx.x;
    if (t >= 128) return;
    int g = t >> 5;
    int k = t & 31;

    float st[32];
#pragma unroll
    for (int i = 0; i < 32; ++i) st[i] = 0.0f;
    st[k] = 1.0f;

#pragma unroll 1
    for (int d = 0; d < 6; ++d) {
#pragma unroll
        for (int w = 0; w < 5; ++w) {
            float th = qp[g * 30 + d * 5 + w] * 0.5f;
            float s, c;
            __sincosf(th, &s, &c);
            const int stride = 16 >> w;
#pragma unroll
            for (int i = 0; i < 32; ++i) {
                if (i & stride) continue;
                float a0 = st[i];
                float a1 = st[i + stride];
                st[i]          = c * a0 - s * a1;
                st[i + stride] = s * a0 + c * a1;
            }
        }
#pragma unroll
        for (int w = 0; w < 4; ++w) {
            const int m = (16 >> w) | (8 >> w);
#pragma unroll
            for (int i = 0; i < 32; ++i)
                if ((i & m) == m) st[i] = -st[i];
        }
    }

    // SMEM half: rows 0..7
#pragma unroll
    for (int j2 = 0; j2 < 4; ++j2) {
        g_M[((g * 32 + k) * 4 + j2) * 2 + 0] = st[2 * j2 + 0];
        g_M[((g * 32 + k) * 4 + j2) * 2 + 1] = st[2 * j2 + 1];
    }
    // CONST half: rows 8..15
#pragma unroll
    for (int j2 = 0; j2 < 4; ++j2) {
        g_M[1024 + ((g * 32 + k) * 4 + j2) * 2 + 0] = st[8 + 2 * j2 + 0];
        g_M[1024 + ((g * 32 + k) * 4 + j2) * 2 + 1] = st[8 + 2 * j2 + 1];
    }
}

// ---------------------------------------------------------------------------
// Packed f32x2 helpers (Blackwell sm_103a)
// ---------------------------------------------------------------------------
__device__ __forceinline__ u64 pk2(float lo, float hi) {
    u64 r;
    asm("mov.b64 %0, {%1, %2};" : "=l"(r) : "f"(lo), "f"(hi));
    return r;
}
__device__ __forceinline__ void upk2(u64 v, float& lo, float& hi) {
    asm("mov.b64 {%0, %1}, %2;" : "=f"(lo), "=f"(hi) : "l"(v));
}
__device__ __forceinline__ u64 fma2(u64 a, u64 b, u64 c) {
    u64 d;
    asm("fma.rn.f32x2 %0, %1, %2, %3;" : "=l"(d) : "l"(a), "l"(b), "l"(c));
    return d;
}
__device__ __forceinline__ u64 mul2(u64 a, u64 b) {
    u64 d;
    asm("mul.rn.f32x2 %0, %1, %2;" : "=l"(d) : "l"(a), "l"(b));
    return d;
}

// Scalar Kronecker factors for ONE batch element.
__device__ __forceinline__ void build_psi_scalar(
    float4 q, float pa[8], float pb[4])
{
    float a0 = q.x, a1 = q.y, a2 = q.z;
    float h0 = 0.5f   * a0;
    float h1 = 0.375f * a0 + 0.125f * a1;
    float h2 = 0.125f * a0 + 0.375f * a1;
    float h3 = 0.375f * a1 + 0.125f * a2;
    float h4 = 0.125f * a1 + 0.375f * a2;
    float c0, s0, c1, s1, c2, s2, c3, s3, c4, s4;
    __sincosf(h0, &s0, &c0);
    __sincosf(h1, &s1, &c1);
    __sincosf(h2, &s2, &c2);
    __sincosf(h3, &s3, &c3);
    __sincosf(h4, &s4, &c4);
    float t00 = c0 * c1, t01 = c0 * s1, t10 = s0 * c1, t11 = s0 * s1;
    pa[0] = t00 * c2; pa[1] = t00 * s2;
    pa[2] = t01 * c2; pa[3] = t01 * s2;
    pa[4] = t10 * c2; pa[5] = t10 * s2;
    pa[6] = t11 * c2; pa[7] = t11 * s2;
    pb[0] = c3 * c4; pb[1] = c3 * s4;
    pb[2] = s3 * c4; pb[3] = s3 * s4;
}

// ---------------------------------------------------------------------------
// Main kernel: 2 batch elements/thread, scalar psi, f32x2 packs TWO OUTPUT
// ROWS. M rows 0..7 from SMEM (LDS.128), rows 8..15 from CONSTANT (LDC.128):
// the two load streams use independent ports, each at half the traffic that
// bound previous rounds.
// ---------------------------------------------------------------------------
__global__ void __launch_bounds__(128, 4) qsrgan_main_kernel(
    const float* __restrict__ in,
    float* __restrict__ out,
    int B)
{
    __shared__ __align__(16) float sM[1024];  // 4 KB: rows 0..7
    {
        const float4* src = (const float4*)g_M;
        float4* dst = (float4*)sM;
#pragma unroll
        for (int i = threadIdx.x; i < 256; i += 128)
            dst[i] = src[i];
    }
    __syncthreads();

    long long b = ((long long)blockIdx.x * 128 + threadIdx.x) * 2;
    if (b >= B) return;
    long long i1 = (b + 1 < B) ? b + 1 : b;

    float4 q0 = __ldg((const float4*)(in + b  * 16));
    float4 q1 = __ldg((const float4*)(in + i1 * 16));

    float paA[8], pbA[4], paB[8], pbB[4];
    build_psi_scalar(q0, paA, pbA);
    build_psi_scalar(q1, paB, pbB);

#pragma unroll 1
    for (int g = 0; g < 4; ++g) {
        // acc[j2][e]: rows (2*j2, 2*j2+1) of element e
        u64 acc[8][2];
#pragma unroll
        for (int j2 = 0; j2 < 8; ++j2) { acc[j2][0] = 0ULL; acc[j2][1] = 0ULL; }

#pragma unroll 8
        for (int k = 0; k < 32; ++k) {
            float pk0 = paA[k >> 2] * pbA[k & 3];
            float pk1 = paB[k >> 2] * pbB[k & 3];
            u64 P0 = pk2(pk0, pk0);
            u64 P1 = pk2(pk1, pk1);

            // rows 0..7 from SMEM
            const ulonglong2* colS = (const ulonglong2*)sM + (g * 32 + k) * 2;
            ulonglong2 s0 = colS[0];
            ulonglong2 s1 = colS[1];
            // rows 8..15 from CONSTANT
            ulonglong2 c0 = cM[(g * 32 + k) * 2 + 0];
            ulonglong2 c1 = cM[(g * 32 + k) * 2 + 1];

            acc[0][0] = fma2(s0.x, P0, acc[0][0]);
            acc[0][1] = fma2(s0.x, P1, acc[0][1]);
            acc[1][0] = fma2(s0.y, P0, acc[1][0]);
            acc[1][1] = fma2(s0.y, P1, acc[1][1]);
            acc[2][0] = fma2(s1.x, P0, acc[2][0]);
            acc[2][1] = fma2(s1.x, P1, acc[2][1]);
            acc[3][0] = fma2(s1.y, P0, acc[3][0]);
            acc[3][1] = fma2(s1.y, P1, acc[3][1]);
            acc[4][0] = fma2(c0.x, P0, acc[4][0]);
            acc[4][1] = fma2(c0.x, P1, acc[4][1]);
            acc[5][0] = fma2(c0.y, P0, acc[5][0]);
            acc[5][1] = fma2(c0.y, P1, acc[5][1]);
            acc[6][0] = fma2(c1.x, P0, acc[6][0]);
            acc[6][1] = fma2(c1.x, P1, acc[6][1]);
            acc[7][0] = fma2(c1.y, P0, acc[7][0]);
            acc[7][1] = fma2(c1.y, P1, acc[7][1]);
        }

        // Epilogue: packed squares, per-element max, scale, store.
        u64 sq0[8], sq1[8];
        float mx0 = 0.0f, mx1 = 0.0f;
#pragma unroll
        for (int j2 = 0; j2 < 8; ++j2) {
            sq0[j2] = mul2(acc[j2][0], acc[j2][0]);
            sq1[j2] = mul2(acc[j2][1], acc[j2][1]);
            float y0, y1, z0, z1;
            upk2(sq0[j2], y0, y1);
            upk2(sq1[j2], z0, z1);
            mx0 = fmaxf(mx0, fmaxf(y0, y1));
            mx1 = fmaxf(mx1, fmaxf(z0, z1));
        }
        float r0 = __fdividef(1.0f, mx0);
        float r1 = __fdividef(1.0f, mx1);

        float* o0 = out + b * 64 + g * 16;
#pragma unroll
        for (int qd = 0; qd < 4; ++qd) {
            float y0, y1, y2, y3;
            upk2(sq0[2 * qd + 0], y0, y1);
            upk2(sq0[2 * qd + 1], y2, y3);
            ((float4*)o0)[qd] = make_float4(y0 * r0, y1 * r0, y2 * r0, y3 * r0);
        }
        if (b + 1 < B) {
            float* o1 = out + i1 * 64 + g * 16;
#pragma unroll
            for (int qd = 0; qd < 4; ++qd) {
                float z0, z1, z2, z3;
                upk2(sq1[2 * qd + 0], z0, z1);
                upk2(sq1[2 * qd + 1], z2, z3);
                ((float4*)o1)[qd] = make_float4(z0 * r1, z1 * r1, z2 * r1, z3 * r1);
            }
        }
    }
}

// ---------------------------------------------------------------------------
extern "C" void kernel_launch(void* const* d_in, const int* in_sizes, int n_in,
                              void* d_out, int out_size)
{
    const float* in = (const float*)d_in[0];   // (B,1,4,4) f32
    const float* qp = (const float*)d_in[1];   // (4, 30) f32
    float* out = (float*)d_out;                // (B, 64) f32

    int B = in_sizes[0] / 16;
    int nthreads = (B + 1) / 2;
    int blocks = (nthreads + 127) / 128;

    precompute_M_kernel<<<1, 128>>>(qp);

    // Stage the const half of M (device-to-device async copy: a legal,
    // graph-capturable memcpy node; no allocation).
    void* gM_ptr = nullptr;
    cudaGetSymbolAddress(&gM_ptr, g_M);
    cudaMemcpyToSymbolAsync(cM, (const char*)gM_ptr + 1024 * sizeof(float),
                            1024 * sizeof(float), 0,
                            cudaMemcpyDeviceToDevice, 0);

    qsrgan_main_kernel<<<blocks, 128>>>(in, out, B);
}